// round 11
// baseline (speedup 1.0000x reference)
#include <cuda_runtime.h>
#include <cstdint>

// Shapes (fixed):
//   log_probs: (128, 64) f32 | ref: (256, 128) i32 | hyp: (256, 128, 64) i32
#define NBATCH 128
#define NSAMP  64
#define NSEQ   (NBATCH * NSAMP)   // 8192
#define RLEN   256
#define HLEN   256
#define SYMS   1024               // tokens in [0,1000)
#define TPD    4                  // token prefetch depth == unroll factor

typedef unsigned long long ull;

__device__ double   d_partial[NBATCH];
__device__ unsigned d_ticket;      // zero at start; winner resets each run

// ---------------------------------------------------------------------------
// One Myers word update. The shift-by-1-with-carry section is written in
// IMAD/IMAD.HI form (x*2+c, __umulhi(x,2)) so it issues on the FMA pipe,
// relieving the alu-pipe issue bound (rt_SMSP=2) that caps this kernel.
// Returns unshifted Ph/Mh (score bit is sampled pre-shift, as in R6..R9).
// ---------------------------------------------------------------------------
__device__ __forceinline__ void myers_word(ull& Pv, ull& Mv, ull Eq,
                                           unsigned& phin, unsigned& mhin,
                                           ull& PhOut, ull& MhOut) {
    ull Xv  = Eq | Mv;
    ull Eqm = Eq | (ull)mhin;                        // carry-in affects low word only
    ull Xh  = (((Eqm & Pv) + Pv) ^ Pv) | Eqm;
    ull Ph  = Mv | ~(Xh | Pv);
    ull Mh  = Pv & Xh;

    unsigned ph_lo = (unsigned)Ph, ph_hi = (unsigned)(Ph >> 32);
    unsigned mh_lo = (unsigned)Mh, mh_hi = (unsigned)(Mh >> 32);

    // carry-outs (bit 63) via IMAD.HI — fma pipe
    unsigned po = __umulhi(ph_hi, 2u);
    unsigned mo = __umulhi(mh_hi, 2u);

    // (X << 1) | carry_in via IMAD — fma pipe
    unsigned nplo = ph_lo * 2u + phin;
    unsigned nphi = ph_hi * 2u + __umulhi(ph_lo, 2u);
    unsigned nmlo = mh_lo * 2u + mhin;
    unsigned nmhi = mh_hi * 2u + __umulhi(mh_lo, 2u);
    ull Phs = ((ull)nphi << 32) | nplo;
    ull Mhs = ((ull)nmhi << 32) | nmlo;

    Pv = Mhs | ~(Xv | Phs);
    Mv = Phs & Xv;
    phin = po; mhin = mo;
    PhOut = Ph; MhOut = Mh;
}

// ---------------------------------------------------------------------------
// Branchless Myers bit-parallel DP over NWA 64-bit words, fixed 256 steps,
// unrolled x4, EOS handled by SEL capture (no data-dependent branches).
// ---------------------------------------------------------------------------
template<int NWA>
__device__ __forceinline__ int myers_run(const ull* __restrict__ sPeq,
                                         const int* __restrict__ hyp,
                                         int n, int pm) {
    ull Pv[NWA], Mv[NWA];
    #pragma unroll
    for (int w = 0; w < NWA; ++w) { Pv[w] = ~0ull; Mv[w] = 0ull; }

    int toks[TPD];
    int tcur = hyp[n] & (SYMS - 1);                       // token for step 0
    #pragma unroll
    for (int k = 0; k < TPD; ++k) toks[k] = hyp[(size_t)(k + 1) * NSEQ + n] & (SYMS - 1);

    ull E[NWA];
    #pragma unroll
    for (int w = 0; w < NWA; ++w) E[w] = sPeq[(tcur << 2) + w];

    int score  = 0;     // running delta vs m; caller adds m
    int scoreF = 0;
    int done   = 0;

    #pragma unroll 1
    for (int hb = 0; hb < HLEN; hb += TPD) {
        #pragma unroll
        for (int j = 0; j < TPD; ++j) {
            const int h = hb + j;

            // prefetch next step's Eq from SMEM (LDS.128 pairs)
            const int t1 = toks[j];
            ull N[NWA];
            if (NWA >= 2) {
                ulonglong2 lo = *reinterpret_cast<const ulonglong2*>(&sPeq[t1 << 2]);
                N[0] = lo.x; N[1] = lo.y;
                if (NWA == 3) N[2] = sPeq[(t1 << 2) + 2];
                if (NWA == 4) {
                    ulonglong2 hi = *reinterpret_cast<const ulonglong2*>(&sPeq[(t1 << 2) + 2]);
                    N[2] = hi.x; N[3] = hi.y;
                }
            } else {
                N[0] = sPeq[t1 << 2];
            }

            // refill ring: token for step h+1+TPD (wrapped; value unused when
            // h+1+TPD >= HLEN because those steps never execute)
            const int sa = (h + 1 + TPD) & (HLEN - 1);
            toks[j] = hyp[(size_t)sa * NSEQ + n] & (SYMS - 1);

            unsigned phin = 1u, mhin = 0u;   // D[i][0] = i boundary
            ull PhT = 0, MhT = 0;
            #pragma unroll
            for (int w = 0; w < NWA; ++w)
                myers_word(Pv[w], Mv[w], E[w], phin, mhin,
                           (w == NWA - 1) ? PhT : PhT, (w == NWA - 1) ? MhT : MhT);
            // score lives in the top word (PhT/MhT hold the last word's values)
            score += (int)((PhT >> pm) & 1ull) - (int)((MhT >> pm) & 1ull);

            // branchless EOS capture: first EOS step (inclusive) latches score
            const int isEos = (tcur == 0);
            scoreF = (isEos & ~done) ? score : scoreF;
            done  |= isEos;

            tcur = t1;
            #pragma unroll
            for (int w = 0; w < NWA; ++w) E[w] = N[w];
        }
    }

    return done ? scoreF : score;
}

// ---------------------------------------------------------------------------
// Fused kernel: block b = batch row b, 64 threads (one per sample).
// ---------------------------------------------------------------------------
__global__ void __launch_bounds__(NSAMP, 1)
mer_loss_kernel(const int* __restrict__ hyp,
                const int* __restrict__ ref,
                const float* __restrict__ logp,
                float* __restrict__ out) {
    __shared__ ull    sPeq[SYMS * 4];   // 32 KB bitmask table
    __shared__ int    sMinEos;
    __shared__ float  sEr[NSAMP];
    __shared__ bool   sLast;
    __shared__ double sSum[NBATCH];

    const int b = blockIdx.x;
    const int s = threadIdx.x;           // 0..63
    const int n = b * NSAMP + s;

    // ---- build Peq in SMEM ----
    if (s == 0) sMinEos = RLEN;
    #pragma unroll
    for (int i = s; i < SYMS * 4; i += NSAMP) sPeq[i] = 0ull;
    __syncthreads();

    int rtok[RLEN / NSAMP];
    #pragma unroll
    for (int k = 0; k < RLEN / NSAMP; ++k) {
        int j = s + k * NSAMP;
        rtok[k] = ref[(size_t)j * NBATCH + b];
        if (rtok[k] == 0) atomicMin(&sMinEos, j);
    }
    __syncthreads();
    const int m = (sMinEos < RLEN) ? (sMinEos + 1) : RLEN;  // INCLUDE_EOS
    #pragma unroll
    for (int k = 0; k < RLEN / NSAMP; ++k) {
        int j = s + k * NSAMP;
        if (j < m)
            atomicOr(&sPeq[((rtok[k] & (SYMS - 1)) << 2) + (j >> 6)], 1ull << (j & 63));
    }
    __syncthreads();

    const int bsel = (m - 1) >> 6;
    const int pm   = (m - 1) & 63;

    // ---- Myers DP, word count dispatched on uniform bsel ----
    int sdel;
    switch (bsel) {
        case 0:  sdel = myers_run<1>(sPeq, hyp, n, pm); break;
        case 1:  sdel = myers_run<2>(sPeq, hyp, n, pm); break;
        case 2:  sdel = myers_run<3>(sPeq, hyp, n, pm); break;
        default: sdel = myers_run<4>(sPeq, hyp, n, pm); break;
    }
    const int score = m + sdel;

    sEr[s] = (float)score / (float)m;
    __syncthreads();

    // ---- per-batch softmax-weighted centered reduction (warp 0) ----
    if (s < 32) {
        int lane = s, base = b * NSAMP;
        float er0 = sEr[lane],         er1 = sEr[lane + 32];
        float lp0 = logp[base + lane], lp1 = logp[base + 32 + lane];

        float mx = fmaxf(lp0, lp1);
        #pragma unroll
        for (int o = 16; o; o >>= 1) mx = fmaxf(mx, __shfl_xor_sync(0xffffffffu, mx, o));

        float e0 = expf(lp0 - mx), e1 = expf(lp1 - mx);
        float se  = e0 + e1;
        float ser = er0 + er1;
        float sep = er0 * e0 + er1 * e1;
        #pragma unroll
        for (int o = 16; o; o >>= 1) {
            se  += __shfl_xor_sync(0xffffffffu, se,  o);
            ser += __shfl_xor_sync(0xffffffffu, ser, o);
            sep += __shfl_xor_sync(0xffffffffu, sep, o);
        }
        if (lane == 0)
            d_partial[b] = (double)sep / (double)se - (double)ser / 64.0;
    }
    __syncthreads();

    // ---- last-block ticket: global mean ----
    if (s == 0) {
        __threadfence();
        unsigned tk = atomicAdd(&d_ticket, 1u);
        sLast = (tk == NBATCH - 1);
    }
    __syncthreads();
    if (sLast) {
        __threadfence();
        #pragma unroll
        for (int k = 0; k < NBATCH / NSAMP; ++k) sSum[s + k * NSAMP] = d_partial[s + k * NSAMP];
        __syncthreads();
        #pragma unroll
        for (int o = 64; o; o >>= 1) {
            if (s < o) sSum[s] += sSum[s + o];
            __syncthreads();
        }
        if (s == 0) {
            out[0] = (float)(sSum[0] / (double)NSEQ);
            d_ticket = 0;   // reset for next graph replay
        }
    }
}

// ---------------------------------------------------------------------------
extern "C" void kernel_launch(void* const* d_in, const int* in_sizes, int n_in,
                              void* d_out, int out_size) {
    const float* logp = (const float*)d_in[0];  // (128,64) f32
    const int*   ref  = (const int*)d_in[1];    // (256,128) i32
    const int*   hyp  = (const int*)d_in[2];    // (256,128,64) i32
    float* out = (float*)d_out;

    mer_loss_kernel<<<NBATCH, NSAMP>>>(hyp, ref, logp, out);
}

// round 12
// speedup vs baseline: 1.1746x; 1.1746x over previous
#include <cuda_runtime.h>
#include <cstdint>

// Shapes (fixed):
//   log_probs: (128, 64) f32 | ref: (256, 128) i32 | hyp: (256, 128, 64) i32
#define NBATCH 128
#define NSAMP  64
#define NSEQ   (NBATCH * NSAMP)   // 8192
#define RLEN   256
#define HLEN   256
#define SYMS   1024               // tokens in [0,1000) -> no masking needed
#define TPD    8                  // token prefetch depth == unroll factor

typedef unsigned long long ull;

__device__ double   d_partial[NBATCH];
__device__ unsigned d_ticket;      // zero at start; winner resets each run

// ---------------------------------------------------------------------------
// Branchless Myers bit-parallel DP over NWA 64-bit words, fixed 256 steps,
// unrolled x8 (wide ptxas scheduling window so consecutive steps' word-chains
// pipeline across the carry wavefront). EOS handled by SEL capture.
// TOP=true (pm==63): score bit == word carry-out, reuse po/mo (saves 4 ops).
// R9 64-bit formulation kept: ptxas emits funnel-SHF + LEA for the shifts and
// auto-alternates IMAD/IADD3 on the add chains (manual IMAD split regressed).
// ---------------------------------------------------------------------------
template<int NWA, bool TOP>
__device__ __forceinline__ int myers_run(const ull* __restrict__ sPeq,
                                         const int* __restrict__ hyp,
                                         int n, int pm) {
    ull Pv[NWA], Mv[NWA];
    #pragma unroll
    for (int w = 0; w < NWA; ++w) { Pv[w] = ~0ull; Mv[w] = 0ull; }

    int toks[TPD];
    int tcur = hyp[n];                                    // token for step 0
    #pragma unroll
    for (int k = 0; k < TPD; ++k) toks[k] = hyp[(size_t)(k + 1) * NSEQ + n];

    ull E[NWA];
    #pragma unroll
    for (int w = 0; w < NWA; ++w) E[w] = sPeq[(tcur << 2) + w];

    int score  = 0;     // running delta vs m; caller adds m
    int scoreF = 0;
    int done   = 0;

    #pragma unroll 1
    for (int hb = 0; hb < HLEN; hb += TPD) {
        #pragma unroll
        for (int j = 0; j < TPD; ++j) {
            const int h = hb + j;

            // prefetch next step's Eq from SMEM (LDS.128 pairs)
            const int t1 = toks[j];
            ull N[NWA];
            if (NWA >= 2) {
                ulonglong2 lo = *reinterpret_cast<const ulonglong2*>(&sPeq[t1 << 2]);
                N[0] = lo.x; N[1] = lo.y;
                if (NWA == 3) N[2] = sPeq[(t1 << 2) + 2];
                if (NWA == 4) {
                    ulonglong2 hi = *reinterpret_cast<const ulonglong2*>(&sPeq[(t1 << 2) + 2]);
                    N[2] = hi.x; N[3] = hi.y;
                }
            } else {
                N[0] = sPeq[t1 << 2];
            }

            // refill ring: token for step h+1+TPD (wrapped; value unused when
            // h+1+TPD >= HLEN because those steps never execute)
            const int sa = (h + 1 + TPD) & (HLEN - 1);
            toks[j] = hyp[(size_t)sa * NSEQ + n];

            // Myers word updates (R6-verified algebra)
            ull phin = 1ull, mhin = 0ull;   // D[i][0] = i boundary
            #pragma unroll
            for (int w = 0; w < NWA; ++w) {
                ull Eq = E[w];
                ull Xv = Eq | Mv[w];
                Eq |= mhin;
                ull Xh = (((Eq & Pv[w]) + Pv[w]) ^ Pv[w]) | Eq;
                ull Ph = Mv[w] | ~(Xh | Pv[w]);
                ull Mh = Pv[w] & Xh;
                ull po = Ph >> 63, mo = Mh >> 63;
                if (w == NWA - 1) {   // score lives in the top word
                    if (TOP)          // pm==63: score bit IS the carry-out
                        score += (int)po - (int)mo;
                    else
                        score += (int)((Ph >> pm) & 1ull) - (int)((Mh >> pm) & 1ull);
                }
                Ph = (Ph << 1) | phin;
                Mh = (Mh << 1) | mhin;
                Pv[w] = Mh | ~(Xv | Ph);
                Mv[w] = Ph & Xv;
                phin = po; mhin = mo;
            }

            // branchless EOS capture: first EOS step (inclusive) latches score
            const int isEos = (tcur == 0);
            scoreF = (isEos & ~done) ? score : scoreF;
            done  |= isEos;

            tcur = t1;
            #pragma unroll
            for (int w = 0; w < NWA; ++w) E[w] = N[w];
        }
    }

    return done ? scoreF : score;
}

// ---------------------------------------------------------------------------
// Fused kernel: block b = batch row b, 64 threads (one per sample).
// ---------------------------------------------------------------------------
__global__ void __launch_bounds__(NSAMP, 1)
mer_loss_kernel(const int* __restrict__ hyp,
                const int* __restrict__ ref,
                const float* __restrict__ logp,
                float* __restrict__ out) {
    __shared__ ull    sPeq[SYMS * 4];   // 32 KB bitmask table
    __shared__ int    sMinEos;
    __shared__ float  sEr[NSAMP];
    __shared__ bool   sLast;
    __shared__ double sSum[NBATCH];

    const int b = blockIdx.x;
    const int s = threadIdx.x;           // 0..63
    const int n = b * NSAMP + s;

    // ---- build Peq in SMEM ----
    if (s == 0) sMinEos = RLEN;
    #pragma unroll
    for (int i = s; i < SYMS * 4; i += NSAMP) sPeq[i] = 0ull;
    __syncthreads();

    int rtok[RLEN / NSAMP];
    #pragma unroll
    for (int k = 0; k < RLEN / NSAMP; ++k) {
        int j = s + k * NSAMP;
        rtok[k] = ref[(size_t)j * NBATCH + b];
        if (rtok[k] == 0) atomicMin(&sMinEos, j);
    }
    __syncthreads();
    const int m = (sMinEos < RLEN) ? (sMinEos + 1) : RLEN;  // INCLUDE_EOS
    #pragma unroll
    for (int k = 0; k < RLEN / NSAMP; ++k) {
        int j = s + k * NSAMP;
        if (j < m)
            atomicOr(&sPeq[(rtok[k] << 2) + (j >> 6)], 1ull << (j & 63));
    }
    __syncthreads();

    const int bsel = (m - 1) >> 6;
    const int pm   = (m - 1) & 63;

    // ---- Myers DP dispatched on uniform (word count, top-bit) ----
    int sdel;
    if (pm == 63) {
        switch (bsel) {
            case 0:  sdel = myers_run<1, true>(sPeq, hyp, n, pm); break;
            case 1:  sdel = myers_run<2, true>(sPeq, hyp, n, pm); break;
            case 2:  sdel = myers_run<3, true>(sPeq, hyp, n, pm); break;
            default: sdel = myers_run<4, true>(sPeq, hyp, n, pm); break;
        }
    } else {
        switch (bsel) {
            case 0:  sdel = myers_run<1, false>(sPeq, hyp, n, pm); break;
            case 1:  sdel = myers_run<2, false>(sPeq, hyp, n, pm); break;
            case 2:  sdel = myers_run<3, false>(sPeq, hyp, n, pm); break;
            default: sdel = myers_run<4, false>(sPeq, hyp, n, pm); break;
        }
    }
    const int score = m + sdel;

    sEr[s] = (float)score / (float)m;
    __syncthreads();

    // ---- per-batch softmax-weighted centered reduction (warp 0) ----
    if (s < 32) {
        int lane = s, base = b * NSAMP;
        float er0 = sEr[lane],         er1 = sEr[lane + 32];
        float lp0 = logp[base + lane], lp1 = logp[base + 32 + lane];

        float mx = fmaxf(lp0, lp1);
        #pragma unroll
        for (int o = 16; o; o >>= 1) mx = fmaxf(mx, __shfl_xor_sync(0xffffffffu, mx, o));

        float e0 = expf(lp0 - mx), e1 = expf(lp1 - mx);
        float se  = e0 + e1;
        float ser = er0 + er1;
        float sep = er0 * e0 + er1 * e1;
        #pragma unroll
        for (int o = 16; o; o >>= 1) {
            se  += __shfl_xor_sync(0xffffffffu, se,  o);
            ser += __shfl_xor_sync(0xffffffffu, ser, o);
            sep += __shfl_xor_sync(0xffffffffu, sep, o);
        }
        if (lane == 0)
            d_partial[b] = (double)sep / (double)se - (double)ser / 64.0;
    }
    __syncthreads();

    // ---- last-block ticket: global mean ----
    if (s == 0) {
        __threadfence();
        unsigned tk = atomicAdd(&d_ticket, 1u);
        sLast = (tk == NBATCH - 1);
    }
    __syncthreads();
    if (sLast) {
        __threadfence();
        #pragma unroll
        for (int k = 0; k < NBATCH / NSAMP; ++k) sSum[s + k * NSAMP] = d_partial[s + k * NSAMP];
        __syncthreads();
        #pragma unroll
        for (int o = 64; o; o >>= 1) {
            if (s < o) sSum[s] += sSum[s + o];
            __syncthreads();
        }
        if (s == 0) {
            out[0] = (float)(sSum[0] / (double)NSEQ);
            d_ticket = 0;   // reset for next graph replay
        }
    }
}

// ---------------------------------------------------------------------------
extern "C" void kernel_launch(void* const* d_in, const int* in_sizes, int n_in,
                              void* d_out, int out_size) {
    const float* logp = (const float*)d_in[0];  // (128,64) f32
    const int*   ref  = (const int*)d_in[1];    // (256,128) i32
    const int*   hyp  = (const int*)d_in[2];    // (256,128,64) i32
    float* out = (float*)d_out;

    mer_loss_kernel<<<NBATCH, NSAMP>>>(hyp, ref, logp, out);
}